// round 1
// baseline (speedup 1.0000x reference)
#include <cuda_runtime.h>
#include <math.h>
#include <stdint.h>

#define T_STEPS 2048
#define BATCH   32
#define HID     256
#define ZCOLS   1024            // 4*HID, gate order f,i,o,c
#define NCTA    128             // recurrence CTAs (all co-resident on 148 SMs)
#define UNITS_PER_CTA 2         // hidden units per CTA
#define REC_THREADS 128

// ---------------- scratch (device globals: no allocations allowed) ----------
__device__ float g_Zx[(size_t)T_STEPS * BATCH * ZCOLS];   // 256 MB: x@Wx4 + b4, row m = t*32+b
__device__ float g_h[2][HID * BATCH];                     // ping-pong h, layout [unit][b]
__device__ int   g_bar_count;                             // monotone arrival counter

// ============================================================================
// Kernel 1: Zx[t*32+b][g*256+j] = sum_k x[b][t][k] * Wg[k][j] + bg[j]
// Classic 128x128 tile SGEMM, BK=16, 256 threads, 8x8 microtile.
// ============================================================================
__global__ __launch_bounds__(256, 2)
void gemm_zx(const float* __restrict__ x,
             const float* __restrict__ Wf, const float* __restrict__ bf,
             const float* __restrict__ Wi, const float* __restrict__ bi,
             const float* __restrict__ Wo, const float* __restrict__ bo,
             const float* __restrict__ Wc, const float* __restrict__ bc)
{
    __shared__ float As[16 * 128];   // [k][m]
    __shared__ float Bs[16 * 128];   // [k][n]

    const int t = threadIdx.x;

    // reset the recurrence grid-barrier counter once per launch (replay-safe)
    if (blockIdx.x == 0 && blockIdx.y == 0 && t == 0) g_bar_count = 0;

    const float* Wg[4] = {Wf, Wi, Wo, Wc};
    const float* bg[4] = {bf, bi, bo, bc};

    const int N0 = blockIdx.x * 128;          // 0..896, never straddles a gate
    const int gate = N0 >> 8;
    const int jb = N0 & 255;
    const float* __restrict__ W = Wg[gate];

    const int M0 = blockIdx.y * 128;
    const int tx = t & 15;                    // n microtile
    const int ty = t >> 4;                    // m microtile

    float acc[8][8];
    #pragma unroll
    for (int i = 0; i < 8; i++)
        #pragma unroll
        for (int j = 0; j < 8; j++) acc[i][j] = 0.f;

    for (int k0 = 0; k0 < 256; k0 += 16) {
        #pragma unroll
        for (int i = 0; i < 2; i++) {
            int f = t + i * 256;
            // A: float4 along k, transpose-store into As[k][m]
            int kq  = f >> 7;                 // 0..3
            int row = f & 127;
            int m   = M0 + row;
            int bb  = m & 31;
            int tt  = m >> 5;
            float4 a = *reinterpret_cast<const float4*>(
                x + ((size_t)bb * T_STEPS + tt) * 256 + k0 + kq * 4);
            As[(kq * 4 + 0) * 128 + row] = a.x;
            As[(kq * 4 + 1) * 128 + row] = a.y;
            As[(kq * 4 + 2) * 128 + row] = a.z;
            As[(kq * 4 + 3) * 128 + row] = a.w;
            // B: float4 along n, direct store into Bs[k][n]
            int kk = f >> 5;                  // 0..15
            int nq = f & 31;                  // 0..31
            *reinterpret_cast<float4*>(&Bs[kk * 128 + nq * 4]) =
                *reinterpret_cast<const float4*>(W + (size_t)(k0 + kk) * 256 + jb + nq * 4);
        }
        __syncthreads();

        #pragma unroll
        for (int k = 0; k < 16; k++) {
            float a[8], bv[8];
            *reinterpret_cast<float4*>(&a[0])  = *reinterpret_cast<float4*>(&As[k * 128 + ty * 8]);
            *reinterpret_cast<float4*>(&a[4])  = *reinterpret_cast<float4*>(&As[k * 128 + ty * 8 + 4]);
            *reinterpret_cast<float4*>(&bv[0]) = *reinterpret_cast<float4*>(&Bs[k * 128 + tx * 8]);
            *reinterpret_cast<float4*>(&bv[4]) = *reinterpret_cast<float4*>(&Bs[k * 128 + tx * 8 + 4]);
            #pragma unroll
            for (int i = 0; i < 8; i++)
                #pragma unroll
                for (int j = 0; j < 8; j++)
                    acc[i][j] = fmaf(a[i], bv[j], acc[i][j]);
        }
        __syncthreads();
    }

    // epilogue: add bias, store fp32
    const float* __restrict__ bias = bg[gate];
    #pragma unroll
    for (int i = 0; i < 8; i++) {
        int m = M0 + ty * 8 + i;
        float* zr = g_Zx + (size_t)m * ZCOLS + N0 + tx * 8;
        float4 v0, v1;
        v0.x = acc[i][0] + bias[jb + tx * 8 + 0];
        v0.y = acc[i][1] + bias[jb + tx * 8 + 1];
        v0.z = acc[i][2] + bias[jb + tx * 8 + 2];
        v0.w = acc[i][3] + bias[jb + tx * 8 + 3];
        v1.x = acc[i][4] + bias[jb + tx * 8 + 4];
        v1.y = acc[i][5] + bias[jb + tx * 8 + 5];
        v1.z = acc[i][6] + bias[jb + tx * 8 + 6];
        v1.w = acc[i][7] + bias[jb + tx * 8 + 7];
        *reinterpret_cast<float4*>(zr)     = v0;
        *reinterpret_cast<float4*>(zr + 4) = v1;
    }
}

// ============================================================================
// Kernel 2: persistent recurrence. 128 CTAs x 128 threads, all co-resident.
// CTA r owns hidden units {2r, 2r+1}. Grid sync via monotone counter.
// ============================================================================
__device__ __forceinline__ void grid_barrier(int target)
{
    __syncthreads();
    if (threadIdx.x == 0) {
        __threadfence();
        atomicAdd(&g_bar_count, 1);
        while (*reinterpret_cast<volatile int*>(&g_bar_count) < target) { }
        __threadfence();
    }
    __syncthreads();
}

__global__ __launch_bounds__(REC_THREADS, 1)
void lstm_rec(const float* __restrict__ Wf, const float* __restrict__ Wi,
              const float* __restrict__ Wo, const float* __restrict__ Wc,
              float* __restrict__ out)
{
    __shared__ float s_Wh[8 * 256];          // [c][k], c = gate*2 + u
    __shared__ float s_h[256 * 32];          // [unit k][b]
    __shared__ float s_z[8 * 32];            // [c][b]
    __shared__ float s_c[2 * 32];            // cell state [u][b]

    const int tid = threadIdx.x;
    const int c0  = blockIdx.x * UNITS_PER_CTA;       // first owned hidden unit
    const float* Wg[4] = {Wf, Wi, Wo, Wc};

    // stage Wh slice once: s_Wh[c][k] = Wg[c/2][(256+k)*256 + c0 + (c&1)]
    for (int idx = tid; idx < 8 * 256; idx += REC_THREADS) {
        int c = idx >> 8;
        int k = idx & 255;
        s_Wh[idx] = Wg[c >> 1][(size_t)(256 + k) * 256 + c0 + (c & 1)];
    }
    if (tid < 64) s_c[tid] = 0.f;
    // zero owned slice of h buffer 0
    if (tid < UNITS_PER_CTA * BATCH) {
        int u = tid >> 5, b = tid & 31;
        g_h[0][(c0 + u) * 32 + b] = 0.f;
        __threadfence();
    }

    int nbar = 1;
    grid_barrier(nbar * NCTA);               // all zeros + weights staged

    const int b = tid & 31;                  // batch lane
    const int p = tid >> 5;                  // gate 0..3 (f,i,o,c)
    const int zc0 = p * HID + c0;

    for (int t = 0; t < T_STEPS; t++) {
        // broadcast h(t) into smem; __ldcg: L1 is not coherent across SMs
        {
            const float4* hb4 = reinterpret_cast<const float4*>(g_h[t & 1]);
            float4* hs4 = reinterpret_cast<float4*>(s_h);
            #pragma unroll
            for (int i = 0; i < 16; i++)
                hs4[i * 128 + tid] = __ldcg(hb4 + i * 128 + tid);
        }
        // start Zx loads early (independent of s_h)
        const float* zrow = g_Zx + ((size_t)t * BATCH + b) * ZCOLS;
        float acc0 = zrow[zc0];
        float acc1 = zrow[zc0 + 1];
        __syncthreads();

        // z[b][2p], z[b][2p+1] += h . Wh
        const float* w0p = &s_Wh[(2 * p) * 256];
        const float* w1p = &s_Wh[(2 * p + 1) * 256];
        #pragma unroll 16
        for (int k = 0; k < 256; k += 4) {
            float4 w0 = *reinterpret_cast<const float4*>(w0p + k);
            float4 w1 = *reinterpret_cast<const float4*>(w1p + k);
            float h0 = s_h[(k + 0) * 32 + b];
            float h1 = s_h[(k + 1) * 32 + b];
            float h2 = s_h[(k + 2) * 32 + b];
            float h3 = s_h[(k + 3) * 32 + b];
            acc0 = fmaf(h0, w0.x, acc0); acc1 = fmaf(h0, w1.x, acc1);
            acc0 = fmaf(h1, w0.y, acc0); acc1 = fmaf(h1, w1.y, acc1);
            acc0 = fmaf(h2, w0.z, acc0); acc1 = fmaf(h2, w1.z, acc1);
            acc0 = fmaf(h3, w0.w, acc0); acc1 = fmaf(h3, w1.w, acc1);
        }
        s_z[(2 * p) * 32 + b]     = acc0;
        s_z[(2 * p + 1) * 32 + b] = acc1;
        __syncthreads();

        // gates + state update + writeback (threads 0..63: (u, b))
        if (tid < 64) {
            int u  = tid >> 5;
            int bb = tid & 31;
            float zf = s_z[(0 + u) * 32 + bb];
            float zi = s_z[(2 + u) * 32 + bb];
            float zo = s_z[(4 + u) * 32 + bb];
            float zg = s_z[(6 + u) * 32 + bb];
            float fg = 1.f / (1.f + expf(-zf));
            float ig = 1.f / (1.f + expf(-zi));
            float og = 1.f / (1.f + expf(-zo));
            float gg = tanhf(zg);
            float cv = fg * s_c[u * 32 + bb] + ig * gg;
            s_c[u * 32 + bb] = cv;
            float hv = og * tanhf(cv);
            g_h[(t + 1) & 1][(c0 + u) * 32 + bb] = hv;
            // reverse time order: out[b][T-1-t][j]
            out[((size_t)bb * T_STEPS + (T_STEPS - 1 - t)) * HID + c0 + u] = hv;
            __threadfence();
        }
        nbar++;
        grid_barrier(nbar * NCTA);
    }
}

// ============================================================================
extern "C" void kernel_launch(void* const* d_in, const int* in_sizes, int n_in,
                              void* d_out, int out_size)
{
    const float* x  = (const float*)d_in[0];
    const float* Wf = (const float*)d_in[1];
    const float* bf = (const float*)d_in[2];
    const float* Wi = (const float*)d_in[3];
    const float* bi = (const float*)d_in[4];
    const float* Wo = (const float*)d_in[5];
    const float* bo = (const float*)d_in[6];
    const float* Wc = (const float*)d_in[7];
    const float* bc = (const float*)d_in[8];
    float* out = (float*)d_out;

    dim3 g1(ZCOLS / 128, (T_STEPS * BATCH) / 128);   // 8 x 512
    gemm_zx<<<g1, 256>>>(x, Wf, bf, Wi, bi, Wo, bo, Wc, bc);
    lstm_rec<<<NCTA, REC_THREADS>>>(Wf, Wi, Wo, Wc, out);
}

// round 2
// speedup vs baseline: 1.1129x; 1.1129x over previous
#include <cuda_runtime.h>
#include <math.h>
#include <stdint.h>

#define T_STEPS 2048
#define BATCH   32
#define HID     256
#define ZCOLS   1024            // 4*HID, gate order f,i,o,c
#define NCTA    128             // recurrence CTAs (all co-resident on 148 SMs)
#define UNITS_PER_CTA 2
#define REC_THREADS 256

// ---------------- scratch (device globals: no allocations allowed) ----------
__device__ float g_Zx[(size_t)T_STEPS * BATCH * ZCOLS];   // 256 MB: x@Wx4 + b4
__device__ float g_h[2][HID * BATCH];                     // ping-pong h, [unit][b]
__device__ int   g_bar_count;                             // monotone arrival counter

// ============================================================================
// Kernel 1: Zx[t*32+b][g*256+j] = sum_k x[b][t][k] * Wg[k][j] + bg[j]
// 128x128 tile SGEMM, BK=16, 256 threads, 8x8 microtile.
// ============================================================================
__global__ __launch_bounds__(256, 2)
void gemm_zx(const float* __restrict__ x,
             const float* __restrict__ Wf, const float* __restrict__ bf,
             const float* __restrict__ Wi, const float* __restrict__ bi,
             const float* __restrict__ Wo, const float* __restrict__ bo,
             const float* __restrict__ Wc, const float* __restrict__ bc)
{
    __shared__ float As[16 * 128];   // [k][m]
    __shared__ float Bs[16 * 128];   // [k][n]

    const int t = threadIdx.x;

    // reset the recurrence grid-barrier counter once per launch (replay-safe)
    if (blockIdx.x == 0 && blockIdx.y == 0 && t == 0) g_bar_count = 0;

    const float* Wg[4] = {Wf, Wi, Wo, Wc};
    const float* bg[4] = {bf, bi, bo, bc};

    const int N0 = blockIdx.x * 128;          // never straddles a gate
    const int gate = N0 >> 8;
    const int jb = N0 & 255;
    const float* __restrict__ W = Wg[gate];

    const int M0 = blockIdx.y * 128;
    const int tx = t & 15;
    const int ty = t >> 4;

    float acc[8][8];
    #pragma unroll
    for (int i = 0; i < 8; i++)
        #pragma unroll
        for (int j = 0; j < 8; j++) acc[i][j] = 0.f;

    for (int k0 = 0; k0 < 256; k0 += 16) {
        #pragma unroll
        for (int i = 0; i < 2; i++) {
            int f = t + i * 256;
            int kq  = f >> 7;
            int row = f & 127;
            int m   = M0 + row;
            int bb  = m & 31;
            int tt  = m >> 5;
            float4 a = *reinterpret_cast<const float4*>(
                x + ((size_t)bb * T_STEPS + tt) * 256 + k0 + kq * 4);
            As[(kq * 4 + 0) * 128 + row] = a.x;
            As[(kq * 4 + 1) * 128 + row] = a.y;
            As[(kq * 4 + 2) * 128 + row] = a.z;
            As[(kq * 4 + 3) * 128 + row] = a.w;
            int kk = f >> 5;
            int nq = f & 31;
            *reinterpret_cast<float4*>(&Bs[kk * 128 + nq * 4]) =
                *reinterpret_cast<const float4*>(W + (size_t)(k0 + kk) * 256 + jb + nq * 4);
        }
        __syncthreads();

        #pragma unroll
        for (int k = 0; k < 16; k++) {
            float a[8], bv[8];
            *reinterpret_cast<float4*>(&a[0])  = *reinterpret_cast<float4*>(&As[k * 128 + ty * 8]);
            *reinterpret_cast<float4*>(&a[4])  = *reinterpret_cast<float4*>(&As[k * 128 + ty * 8 + 4]);
            *reinterpret_cast<float4*>(&bv[0]) = *reinterpret_cast<float4*>(&Bs[k * 128 + tx * 8]);
            *reinterpret_cast<float4*>(&bv[4]) = *reinterpret_cast<float4*>(&Bs[k * 128 + tx * 8 + 4]);
            #pragma unroll
            for (int i = 0; i < 8; i++)
                #pragma unroll
                for (int j = 0; j < 8; j++)
                    acc[i][j] = fmaf(a[i], bv[j], acc[i][j]);
        }
        __syncthreads();
    }

    const float* __restrict__ bias = bg[gate];
    #pragma unroll
    for (int i = 0; i < 8; i++) {
        int m = M0 + ty * 8 + i;
        float* zr = g_Zx + (size_t)m * ZCOLS + N0 + tx * 8;
        float4 v0, v1;
        v0.x = acc[i][0] + bias[jb + tx * 8 + 0];
        v0.y = acc[i][1] + bias[jb + tx * 8 + 1];
        v0.z = acc[i][2] + bias[jb + tx * 8 + 2];
        v0.w = acc[i][3] + bias[jb + tx * 8 + 3];
        v1.x = acc[i][4] + bias[jb + tx * 8 + 4];
        v1.y = acc[i][5] + bias[jb + tx * 8 + 5];
        v1.z = acc[i][6] + bias[jb + tx * 8 + 6];
        v1.w = acc[i][7] + bias[jb + tx * 8 + 7];
        *reinterpret_cast<float4*>(zr)     = v0;
        *reinterpret_cast<float4*>(zr + 4) = v1;
    }
}

// ============================================================================
// Kernel 2: persistent recurrence, 128 CTAs x 256 threads.
// Grid sync: red.release arrival + ld.acquire poll (no MEMBAR.GPU).
// ============================================================================
__device__ __forceinline__ void grid_barrier(int target)
{
    __syncthreads();
    if (threadIdx.x == 0) {
        asm volatile("red.release.gpu.global.add.s32 [%0], %1;"
                     :: "l"(&g_bar_count), "r"(1) : "memory");
        int v;
        do {
            asm volatile("ld.acquire.gpu.global.b32 %0, [%1];"
                         : "=r"(v) : "l"((int*)&g_bar_count) : "memory");
        } while (v < target);
    }
    __syncthreads();
}

#define WPAD 260   // s_Wh row pitch (260 % 32 == 4 -> conflict-free f4 loads)
#define PPAD 33    // s_part row pitch

__global__ __launch_bounds__(REC_THREADS, 1)
void lstm_rec(const float* __restrict__ Wf, const float* __restrict__ Wi,
              const float* __restrict__ Wo, const float* __restrict__ Wc,
              float* __restrict__ out)
{
    __shared__ float s_Wh[8 * WPAD];     // [c][k], c = 2*gate + u
    __shared__ float s_h[256 * 32];      // [k][b]
    __shared__ float s_part[32 * PPAD];  // [kq*8+c][b]
    __shared__ float s_c[2 * 32];        // cell state [u][b]

    const int tid = threadIdx.x;
    const int c0  = blockIdx.x * UNITS_PER_CTA;
    const float* Wg[4] = {Wf, Wi, Wo, Wc};

    // stage Wh slice once: s_Wh[c][k] = Wg[c/2][(256+k)*256 + c0 + (c&1)]
    for (int idx = tid; idx < 8 * 256; idx += REC_THREADS) {
        int c = idx >> 8;
        int k = idx & 255;
        s_Wh[c * WPAD + k] = Wg[c >> 1][(size_t)(256 + k) * 256 + c0 + (c & 1)];
    }
    if (tid < 64) s_c[tid] = 0.f;
    if (tid < UNITS_PER_CTA * BATCH) {
        int u = tid >> 5, b = tid & 31;
        g_h[0][(c0 + u) * 32 + b] = 0.f;
    }

    int nbar = 1;
    grid_barrier(nbar * NCTA);           // weights staged + h0 zeroed everywhere

    // thread role: kq = k-range (64 k's), c = local z-col (0..7), bq = batch quad
    const int kq = tid >> 6;
    const int r  = tid & 63;
    const int c  = r >> 3;
    const int bq = r & 7;
    const int colg = (c >> 1) * HID + c0 + (c & 1);   // global z column

    const float* wrow = s_Wh + c * WPAD + kq * 64;
    const float* hcol = s_h + (kq * 64) * 32 + 4 * bq;
    float* prow = s_part + (kq * 8 + c) * PPAD + 4 * bq;

    for (int t = 0; t < T_STEPS; t++) {
        // Zx for this (c, batch-quad): issue early (overlaps with h broadcast)
        float a0, a1, a2, a3;
        if (kq == 0) {
            const float* z = g_Zx + ((size_t)t * BATCH + 4 * bq) * ZCOLS + colg;
            a0 = __ldcg(z);
            a1 = __ldcg(z + ZCOLS);
            a2 = __ldcg(z + 2 * ZCOLS);
            a3 = __ldcg(z + 3 * ZCOLS);
        } else {
            a0 = a1 = a2 = a3 = 0.f;
        }

        // broadcast h(t) into smem (L1 is not coherent across SMs -> __ldcg)
        {
            const float4* hb4 = reinterpret_cast<const float4*>(g_h[t & 1]);
            float4* hs4 = reinterpret_cast<float4*>(s_h);
            #pragma unroll
            for (int i = 0; i < 8; i++)
                hs4[i * 256 + tid] = __ldcg(hb4 + i * 256 + tid);
        }
        __syncthreads();

        // partial dot over this thread's 64-k range, 4 batches at once
        #pragma unroll
        for (int k4 = 0; k4 < 16; k4++) {
            float4 w = *reinterpret_cast<const float4*>(wrow + k4 * 4);
            float4 h0 = *reinterpret_cast<const float4*>(hcol + (k4 * 4 + 0) * 32);
            a0 = fmaf(w.x, h0.x, a0); a1 = fmaf(w.x, h0.y, a1);
            a2 = fmaf(w.x, h0.z, a2); a3 = fmaf(w.x, h0.w, a3);
            float4 h1 = *reinterpret_cast<const float4*>(hcol + (k4 * 4 + 1) * 32);
            a0 = fmaf(w.y, h1.x, a0); a1 = fmaf(w.y, h1.y, a1);
            a2 = fmaf(w.y, h1.z, a2); a3 = fmaf(w.y, h1.w, a3);
            float4 h2 = *reinterpret_cast<const float4*>(hcol + (k4 * 4 + 2) * 32);
            a0 = fmaf(w.z, h2.x, a0); a1 = fmaf(w.z, h2.y, a1);
            a2 = fmaf(w.z, h2.z, a2); a3 = fmaf(w.z, h2.w, a3);
            float4 h3 = *reinterpret_cast<const float4*>(hcol + (k4 * 4 + 3) * 32);
            a0 = fmaf(w.w, h3.x, a0); a1 = fmaf(w.w, h3.y, a1);
            a2 = fmaf(w.w, h3.z, a2); a3 = fmaf(w.w, h3.w, a3);
        }
        prow[0] = a0; prow[1] = a1; prow[2] = a2; prow[3] = a3;
        __syncthreads();

        // gates + state update + writeback: threads (u, b)
        if (tid < 64) {
            int u  = tid >> 5;
            int bb = tid & 31;
            float zf = 0.f, zi = 0.f, zo = 0.f, zg = 0.f;
            #pragma unroll
            for (int q = 0; q < 4; q++) {
                zf += s_part[(q * 8 + 0 + u) * PPAD + bb];
                zi += s_part[(q * 8 + 2 + u) * PPAD + bb];
                zo += s_part[(q * 8 + 4 + u) * PPAD + bb];
                zg += s_part[(q * 8 + 6 + u) * PPAD + bb];
            }
            float fg = 1.f / (1.f + __expf(-zf));
            float ig = 1.f / (1.f + __expf(-zi));
            float og = 1.f / (1.f + __expf(-zo));
            float gg = tanhf(zg);
            float cv = fg * s_c[u * 32 + bb] + ig * gg;
            s_c[u * 32 + bb] = cv;
            float hv = og * tanhf(cv);
            g_h[(t + 1) & 1][(c0 + u) * 32 + bb] = hv;
            // reverse time order: out[b][T-1-t][j]
            out[((size_t)bb * T_STEPS + (T_STEPS - 1 - t)) * HID + c0 + u] = hv;
        }
        nbar++;
        grid_barrier(nbar * NCTA);   // release publishes h writes; acquire makes them visible
    }
}

// ============================================================================
extern "C" void kernel_launch(void* const* d_in, const int* in_sizes, int n_in,
                              void* d_out, int out_size)
{
    const float* x  = (const float*)d_in[0];
    const float* Wf = (const float*)d_in[1];
    const float* bf = (const float*)d_in[2];
    const float* Wi = (const float*)d_in[3];
    const float* bi = (const float*)d_in[4];
    const float* Wo = (const float*)d_in[5];
    const float* bo = (const float*)d_in[6];
    const float* Wc = (const float*)d_in[7];
    const float* bc = (const float*)d_in[8];
    float* out = (float*)d_out;

    dim3 g1(ZCOLS / 128, (T_STEPS * BATCH) / 128);   // 8 x 512
    gemm_zx<<<g1, 256>>>(x, Wf, bf, Wi, bi, Wo, bo, Wc, bc);
    lstm_rec<<<NCTA, REC_THREADS>>>(Wf, Wi, Wo, Wc, out);
}